// round 6
// baseline (speedup 1.0000x reference)
#include <cuda_runtime.h>
#include <math.h>

#define Bb 2
#define Ll 384
#define Dd 128
#define NH 8
#define DHSc 16
#define NPC 12            // DHP*3
#define FEAT 1280
#define KSPLIT 5
#define OUTROWS (Bb*Ll)
#define JC 64             // j-chunk for logit kernel
#define ESTR 132          // padded smem row stride (floats) for e tiles

// ---------------- scratch (no allocations allowed) ----------------
static __device__ __align__(16) float g_qs[Bb*NH*Ll*DHSc];
static __device__ __align__(16) float g_ks[Bb*NH*Ll*DHSc];
static __device__ __align__(16) float g_vs[Bb*NH*Ll*DHSc];
static __device__ __align__(16) float g_qp[Bb*NH*Ll*NPC];
static __device__ __align__(16) float g_kp[Bb*NH*Ll*NPC];
static __device__ __align__(16) float g_vp[Bb*NH*Ll*NPC];
static __device__ __align__(16) float g_qq[Bb*NH*Ll];
static __device__ __align__(16) float g_kk[Bb*NH*Ll];
static __device__ __align__(16) float g_logit[(size_t)Bb*NH*Ll*Ll];
static __device__ __align__(16) float g_attn[(size_t)Bb*Ll*Ll*NH];   // [bi][j][n]
static __device__ __align__(16) float g_feat[Bb*Ll*FEAT];
static __device__ __align__(16) float g_part[KSPLIT*OUTROWS*Dd];

// ---------------- kernel 1: projections ----------------
__global__ __launch_bounds__(128) void proj_kernel(
    const float* __restrict__ x, const float* __restrict__ r, const float* __restrict__ t,
    const float* __restrict__ Wqs, const float* __restrict__ Wks, const float* __restrict__ Wvs,
    const float* __restrict__ Wqp, const float* __restrict__ Wkp, const float* __restrict__ Wvp)
{
    int bi = blockIdx.x;
    int b = bi / Ll, i = bi % Ll;
    int tid = threadIdx.x;
    __shared__ float xs[Dd];
    __shared__ float rs[9], ts[3];
    __shared__ float xp[96];
    __shared__ float sq[96];
    xs[tid] = x[bi * Dd + tid];
    if (tid < 9) rs[tid] = r[bi * 9 + tid];
    else if (tid >= 16 && tid < 19) ts[tid - 16] = t[bi * 3 + (tid - 16)];
    __syncthreads();
    {
        float a0 = 0.f, a1 = 0.f, a2 = 0.f;
        #pragma unroll 4
        for (int k = 0; k < Dd; k++) {
            float xv = xs[k];
            a0 += xv * Wqs[k * Dd + tid];
            a1 += xv * Wks[k * Dd + tid];
            a2 += xv * Wvs[k * Dd + tid];
        }
        int n = tid >> 4, d = tid & 15;
        int o = ((b * NH + n) * Ll + i) * DHSc + d;
        g_qs[o] = a0; g_ks[o] = a1; g_vs[o] = a2;
    }
    #pragma unroll
    for (int w = 0; w < 3; w++) {
        const float* W = (w == 0) ? Wqp : (w == 1) ? Wkp : Wvp;
        float* dst = (w == 0) ? g_qp : (w == 1) ? g_kp : g_vp;
        if (tid < 96) {
            float a = 0.f;
            #pragma unroll 4
            for (int k = 0; k < Dd; k++) a += xs[k] * W[k * 96 + tid];
            xp[tid] = a;
        }
        __syncthreads();
        if (tid < 96) {
            int n = tid / 12, pc = tid % 12, p = pc / 3, c = pc % 3;
            const float* xb = &xp[n * 12 + p * 3];
            float v = xb[0] * rs[c] + xb[1] * rs[3 + c] + xb[2] * rs[6 + c] + ts[c];
            dst[((b * NH + n) * Ll + i) * NPC + pc] = v;
            sq[tid] = v * v;
        }
        __syncthreads();
        if (w < 2 && tid < NH) {
            float s = 0.f;
            #pragma unroll
            for (int m = 0; m < 12; m++) s += sq[tid * 12 + m];
            (w == 0 ? g_qq : g_kk)[(b * NH + tid) * Ll + i] = s;
        }
        __syncthreads();
    }
}

// ---------------- kernel 2: logits (bias + scalar + point), grid (768, 6) ----------------
__global__ __launch_bounds__(256) void logit_kernel(
    const float* __restrict__ e, const float* __restrict__ Wb,
    const float* __restrict__ gamma)
{
    int bi = blockIdx.x;
    int b = bi / Ll, i = bi % Ll;
    int j0 = blockIdx.y * JC;
    int tid = threadIdx.x;

    __shared__ __align__(16) float es[JC * ESTR];    // e tile, padded
    __shared__ __align__(16) float wbt[NH * ESTR];   // Wb transposed [n][d], padded
    __shared__ float sqs[NH * DHSc];
    __shared__ float sqp[NH * NPC];
    __shared__ float sqq[NH], gam[NH];

    // Wb transposed
    for (int m = tid; m < Dd * NH; m += 256) {
        int d = m >> 3, n = m & 7;
        wbt[n * ESTR + d] = Wb[m];
    }
    if (tid < 128) {
        int n = tid >> 4, d = tid & 15;
        sqs[tid] = g_qs[((b * NH + n) * Ll + i) * DHSc + d];
    } else if (tid < 224) {
        int m = tid - 128, n = m / 12, pc = m % 12;
        sqp[m] = g_qp[((b * NH + n) * Ll + i) * NPC + pc];
    } else if (tid < 232) {
        int n = tid - 224;
        sqq[n] = g_qq[(b * NH + n) * Ll + i];
        gam[n] = gamma[n];
    }
    // e tile: 64 rows x 128 floats
    {
        const float4* esrc = (const float4*)(e + ((size_t)bi * Ll + j0) * Dd);
        for (int m = tid; m < JC * 32; m += 256) {
            int row = m >> 5, dq = m & 31;
            *(float4*)&es[row * ESTR + dq * 4] = esrc[m];
        }
    }
    __syncthreads();

    int jl = tid >> 2, g = tid & 3, j = j0 + jl;
    // bias for heads g and g+4
    float b0 = 0.f, b1 = 0.f;
    {
        const float* er = &es[jl * ESTR];
        const float* w0 = &wbt[g * ESTR];
        const float* w1 = &wbt[(g + 4) * ESTR];
        #pragma unroll 8
        for (int d = 0; d < Dd; d += 4) {
            float4 ev = *(const float4*)&er[d];
            float4 wa = *(const float4*)&w0[d];
            float4 wc = *(const float4*)&w1[d];
            b0 += ev.x * wa.x + ev.y * wa.y + ev.z * wa.z + ev.w * wa.w;
            b1 += ev.x * wc.x + ev.y * wc.y + ev.z * wc.z + ev.w * wc.w;
        }
    }
    #pragma unroll
    for (int h = 0; h < 2; h++) {
        int n = g + h * 4;
        float bias = h ? b1 : b0;
        const float4* kr = (const float4*)&g_ks[((b * NH + n) * Ll + j) * DHSc];
        float4 k0 = kr[0], k1 = kr[1], k2 = kr[2], k3 = kr[3];
        const float* q = &sqs[n * DHSc];
        float s = q[0]*k0.x + q[1]*k0.y + q[2]*k0.z + q[3]*k0.w
                + q[4]*k1.x + q[5]*k1.y + q[6]*k1.z + q[7]*k1.w
                + q[8]*k2.x + q[9]*k2.y + q[10]*k2.z + q[11]*k2.w
                + q[12]*k3.x + q[13]*k3.y + q[14]*k3.z + q[15]*k3.w;
        const float4* kp = (const float4*)&g_kp[((b * NH + n) * Ll + j) * NPC];
        float4 p0 = kp[0], p1 = kp[1], p2 = kp[2];
        const float* qp = &sqp[n * NPC];
        float cr = qp[0]*p0.x + qp[1]*p0.y + qp[2]*p0.z + qp[3]*p0.w
                 + qp[4]*p1.x + qp[5]*p1.y + qp[6]*p1.z + qp[7]*p1.w
                 + qp[8]*p2.x + qp[9]*p2.y + qp[10]*p2.z + qp[11]*p2.w;
        float d2 = sqq[n] + g_kk[(b * NH + n) * Ll + j] - 2.f * cr;
        g_logit[((size_t)(b * NH + n) * Ll + i) * Ll + j] =
            0.5773502691896258f * (0.25f * s + bias - 0.125f * gam[n] * d2);
    }
}

// ---------------- kernel 3: softmax + out_scalar + op + point/norm ----------------
__global__ __launch_bounds__(256) void mid_kernel(
    const float* __restrict__ r, const float* __restrict__ t)
{
    int bi = blockIdx.x;
    int b = bi / Ll, i = bi % Ll;
    int tid = threadIdx.x;
    int warp = tid >> 5, lane = tid & 31;

    __shared__ __align__(16) float attn_s[NH * Ll];  // [n][j]
    __shared__ __align__(16) float attn_t[Ll * NH];  // [j][n]
    __shared__ float rs[9], ts[3];
    __shared__ float op_s[96], opl2[96];
    __shared__ float ps[256], pp[192];

    // load logits (L2-hot)
    for (int m = tid; m < NH * Ll / 4; m += 256) {
        int n = m / (Ll / 4), jq = m % (Ll / 4);
        *(float4*)&attn_s[n * Ll + jq * 4] =
            *(const float4*)&g_logit[((size_t)(b * NH + n) * Ll + i) * Ll + jq * 4];
    }
    if (tid >= 224 && tid < 233) rs[tid - 224] = r[bi * 9 + (tid - 224)];
    else if (tid >= 240 && tid < 243) ts[tid - 240] = t[bi * 3 + (tid - 240)];
    __syncthreads();

    // softmax: warp w = head w
    {
        float* row = &attn_s[warp * Ll];
        float mx = -1e30f;
        for (int j = lane; j < Ll; j += 32) mx = fmaxf(mx, row[j]);
        #pragma unroll
        for (int off = 16; off > 0; off >>= 1)
            mx = fmaxf(mx, __shfl_xor_sync(0xffffffffu, mx, off));
        float sum = 0.f;
        for (int j = lane; j < Ll; j += 32) {
            float ex = __expf(row[j] - mx);
            row[j] = ex;
            sum += ex;
        }
        #pragma unroll
        for (int off = 16; off > 0; off >>= 1)
            sum += __shfl_xor_sync(0xffffffffu, sum, off);
        float inv = 1.f / sum;
        for (int j = lane; j < Ll; j += 32) {
            float a = row[j] * inv;
            row[j] = a;
            attn_t[j * NH + warp] = a;
        }
    }
    __syncthreads();

    // coalesced store of attn [j][n] for pair kernel
    {
        float* dst = &g_attn[(size_t)bi * Ll * NH];
        const float4* src = (const float4*)attn_t;
        float4* d4 = (float4*)dst;
        for (int m = tid; m < Ll * NH / 4; m += 256) d4[m] = src[m];
    }

    float* feat = &g_feat[bi * FEAT];

    // out_scalar (attn @ vs) and op (attn @ vp), split over j-halves
    {
        {
            int jh = tid >> 7, dt = tid & 127;
            int n = dt >> 4, d = dt & 15;
            const float* row = &attn_s[n * Ll];
            const float* vb = &g_vs[((b * NH + n) * Ll) * DHSc + d];
            float a = 0.f;
            int j0 = jh * 192;
            #pragma unroll 8
            for (int j = j0; j < j0 + 192; j++) a += row[j] * vb[j * DHSc];
            ps[tid] = a;
        }
        if (tid < 192) {
            int jh = tid / 96, m = tid - jh * 96;
            int n = m / 12, pc = m % 12;
            const float* row = &attn_s[n * Ll];
            const float* vb = &g_vp[((b * NH + n) * Ll) * NPC + pc];
            float a = 0.f;
            int j0 = jh * 192;
            #pragma unroll 8
            for (int j = j0; j < j0 + 192; j++) a += row[j] * vb[j * NPC];
            pp[tid] = a;
        }
    }
    __syncthreads();
    if (tid < 128) feat[tid] = ps[tid] + ps[128 + tid];          // out_scalar
    else if (tid < 224) { int m = tid - 128; op_s[m] = pp[m] + pp[96 + m]; }
    __syncthreads();

    // op_local (inverse rotation) + norm
    if (tid < 96) {
        int pc = tid % 12, nb = tid - pc;
        int p3 = (pc / 3) * 3, c = pc % 3;
        const float* ob = &op_s[nb + p3];
        float v = (ob[0] - ts[0]) * rs[c * 3 + 0]
                + (ob[1] - ts[1]) * rs[c * 3 + 1]
                + (ob[2] - ts[2]) * rs[c * 3 + 2];
        feat[1152 + tid] = v;
        opl2[tid] = v * v;
    }
    __syncthreads();
    if (tid < 32) {
        int base = (tid >> 2) * 12 + (tid & 3) * 3;
        feat[1248 + tid] = sqrtf(opl2[base] + opl2[base + 1] + opl2[base + 2]);
    }
}

// ---------------- kernel 4: out_pair = attn @ e, grid (768, 4) ----------------
__global__ __launch_bounds__(256) void pair_kernel(const float* __restrict__ e)
{
    int bi = blockIdx.x;
    int d0 = blockIdx.y * 32;
    int tid = threadIdx.x;
    int warp = tid >> 5, lane = tid & 31;

    __shared__ __align__(16) float at[Ll * NH];     // attn [j][n]
    __shared__ __align__(16) float red[8 * NH * 32];

    {
        const float4* src = (const float4*)&g_attn[(size_t)bi * Ll * NH];
        float4* dst = (float4*)at;
        for (int m = tid; m < Ll * NH / 4; m += 256) dst[m] = src[m];
    }
    __syncthreads();

    float acc[NH] = {0.f, 0.f, 0.f, 0.f, 0.f, 0.f, 0.f, 0.f};
    const float* eb = e + (size_t)bi * Ll * Dd + d0 + lane;
    #pragma unroll 4
    for (int j = warp; j < Ll; j += 8) {
        float ev = eb[(size_t)j * Dd];
        float4 a0 = *(const float4*)&at[j * NH];
        float4 a1 = *(const float4*)&at[j * NH + 4];
        acc[0] += a0.x * ev; acc[1] += a0.y * ev; acc[2] += a0.z * ev; acc[3] += a0.w * ev;
        acc[4] += a1.x * ev; acc[5] += a1.y * ev; acc[6] += a1.z * ev; acc[7] += a1.w * ev;
    }
    #pragma unroll
    for (int n = 0; n < NH; n++) red[warp * (NH * 32) + n * 32 + lane] = acc[n];
    __syncthreads();
    {
        int n = tid >> 5, l = tid & 31;
        float s = 0.f;
        #pragma unroll
        for (int w = 0; w < 8; w++) s += red[w * (NH * 32) + n * 32 + l];
        g_feat[bi * FEAT + 128 + n * Dd + d0 + l] = s;
    }
}

// ---------------- kernel 5a: partial out GEMM (k-split) ----------------
#define TMR 8
#define KC 64
__global__ __launch_bounds__(256) void out_part_kernel(const float* __restrict__ Wo)
{
    int row0 = blockIdx.x * TMR;
    int kbase = blockIdx.y * (FEAT / KSPLIT);
    int tid = threadIdx.x;
    int tx = tid & 31;
    int ty = tid >> 5;
    __shared__ __align__(16) float As[TMR * KC];
    __shared__ __align__(16) float Bs[KC * Dd];
    float acc0 = 0.f, acc1 = 0.f, acc2 = 0.f, acc3 = 0.f;
    #pragma unroll
    for (int tile = 0; tile < (FEAT / KSPLIT) / KC; tile++) {
        int k0 = kbase + tile * KC;
        for (int m = tid; m < TMR * KC; m += 256) {
            int rr = m >> 6, kk = m & (KC - 1);
            As[m] = g_feat[(row0 + rr) * FEAT + k0 + kk];
        }
        {
            const float4* wsrc = (const float4*)(Wo + (size_t)k0 * Dd);
            float4* bdst = (float4*)Bs;
            for (int m = tid; m < KC * Dd / 4; m += 256) bdst[m] = wsrc[m];
        }
        __syncthreads();
        #pragma unroll 4
        for (int kk = 0; kk < KC; kk++) {
            float av = As[ty * KC + kk];
            float4 bv = *(const float4*)&Bs[kk * Dd + tx * 4];
            acc0 += av * bv.x; acc1 += av * bv.y; acc2 += av * bv.z; acc3 += av * bv.w;
        }
        __syncthreads();
    }
    int row = row0 + ty;
    *(float4*)&g_part[((size_t)blockIdx.y * OUTROWS + row) * Dd + tx * 4] =
        make_float4(acc0, acc1, acc2, acc3);
}

// ---------------- kernel 5b: reduce partials + bias ----------------
__global__ __launch_bounds__(256) void out_reduce_kernel(
    const float* __restrict__ bo, float* __restrict__ out)
{
    int idx = blockIdx.x * 256 + threadIdx.x;
    int c = idx & (Dd - 1);
    float a = bo[c];
    #pragma unroll
    for (int s = 0; s < KSPLIT; s++) a += g_part[s * (OUTROWS * Dd) + idx];
    out[idx] = a;
}

// ---------------- launch ----------------
extern "C" void kernel_launch(void* const* d_in, const int* in_sizes, int n_in,
                              void* d_out, int out_size) {
    const float* x     = (const float*)d_in[0];
    const float* e     = (const float*)d_in[1];
    const float* r     = (const float*)d_in[2];
    const float* t     = (const float*)d_in[3];
    const float* Wqs   = (const float*)d_in[4];
    const float* Wks   = (const float*)d_in[5];
    const float* Wvs   = (const float*)d_in[6];
    const float* Wb    = (const float*)d_in[7];
    const float* Wqp   = (const float*)d_in[8];
    const float* Wkp   = (const float*)d_in[9];
    const float* Wvp   = (const float*)d_in[10];
    const float* gamma = (const float*)d_in[11];
    const float* Wo    = (const float*)d_in[12];
    const float* bo    = (const float*)d_in[13];
    float* out = (float*)d_out;

    proj_kernel<<<Bb * Ll, 128>>>(x, r, t, Wqs, Wks, Wvs, Wqp, Wkp, Wvp);
    logit_kernel<<<dim3(Bb * Ll, Ll / JC), 256>>>(e, Wb, gamma);
    mid_kernel<<<Bb * Ll, 256>>>(r, t);
    pair_kernel<<<dim3(Bb * Ll, 4), 256>>>(e);
    out_part_kernel<<<dim3((Bb * Ll) / TMR, KSPLIT), 256>>>(Wo);
    out_reduce_kernel<<<(OUTROWS * Dd) / 256, 256>>>(bo, out);
}

// round 7
// speedup vs baseline: 1.0361x; 1.0361x over previous
#include <cuda_runtime.h>
#include <math.h>

#define Bb 2
#define Ll 384
#define Dd 128
#define NH 8
#define DHSc 16
#define NPC 12            // DHP*3
#define FEAT 1280
#define KSPLIT 5
#define OUTROWS (Bb*Ll)
#define JC 48             // j-chunk for fused kernel
#define NCH (Ll/JC)       // 8 chunks
#define ESTR 132          // padded smem row stride (floats) for e tiles

// ---------------- scratch (no allocations allowed) ----------------
static __device__ __align__(16) float g_qs[Bb*NH*Ll*DHSc];
static __device__ __align__(16) float g_ks[Bb*NH*Ll*DHSc];
static __device__ __align__(16) float g_vs[Bb*NH*Ll*DHSc];
static __device__ __align__(16) float g_qp[Bb*NH*Ll*NPC];
static __device__ __align__(16) float g_kp[Bb*NH*Ll*NPC];
static __device__ __align__(16) float g_vp[Bb*NH*Ll*NPC];
static __device__ __align__(16) float g_qq[Bb*NH*Ll];
static __device__ __align__(16) float g_kk[Bb*NH*Ll];
static __device__ __align__(16) float g_logit[(size_t)Bb*NH*Ll*Ll];  // pre-logit (scalar+point terms)
static __device__ __align__(16) float g_feat[Bb*Ll*FEAT];
static __device__ __align__(16) float g_part[KSPLIT*OUTROWS*Dd];

// ---------------- kernel 1: projections ----------------
__global__ __launch_bounds__(128) void proj_kernel(
    const float* __restrict__ x, const float* __restrict__ r, const float* __restrict__ t,
    const float* __restrict__ Wqs, const float* __restrict__ Wks, const float* __restrict__ Wvs,
    const float* __restrict__ Wqp, const float* __restrict__ Wkp, const float* __restrict__ Wvp)
{
    int bi = blockIdx.x;
    int b = bi / Ll, i = bi % Ll;
    int tid = threadIdx.x;
    __shared__ float xs[Dd];
    __shared__ float rs[9], ts[3];
    __shared__ float xp[96];
    __shared__ float sq[96];
    xs[tid] = x[bi * Dd + tid];
    if (tid < 9) rs[tid] = r[bi * 9 + tid];
    else if (tid >= 16 && tid < 19) ts[tid - 16] = t[bi * 3 + (tid - 16)];
    __syncthreads();
    {
        float a0 = 0.f, a1 = 0.f, a2 = 0.f;
        #pragma unroll 4
        for (int k = 0; k < Dd; k++) {
            float xv = xs[k];
            a0 += xv * Wqs[k * Dd + tid];
            a1 += xv * Wks[k * Dd + tid];
            a2 += xv * Wvs[k * Dd + tid];
        }
        int n = tid >> 4, d = tid & 15;
        int o = ((b * NH + n) * Ll + i) * DHSc + d;
        g_qs[o] = a0; g_ks[o] = a1; g_vs[o] = a2;
    }
    #pragma unroll
    for (int w = 0; w < 3; w++) {
        const float* W = (w == 0) ? Wqp : (w == 1) ? Wkp : Wvp;
        float* dst = (w == 0) ? g_qp : (w == 1) ? g_kp : g_vp;
        if (tid < 96) {
            float a = 0.f;
            #pragma unroll 4
            for (int k = 0; k < Dd; k++) a += xs[k] * W[k * 96 + tid];
            xp[tid] = a;
        }
        __syncthreads();
        if (tid < 96) {
            int n = tid / 12, pc = tid % 12, p = pc / 3, c = pc % 3;
            const float* xb = &xp[n * 12 + p * 3];
            float v = xb[0] * rs[c] + xb[1] * rs[3 + c] + xb[2] * rs[6 + c] + ts[c];
            dst[((b * NH + n) * Ll + i) * NPC + pc] = v;
            sq[tid] = v * v;
        }
        __syncthreads();
        if (w < 2 && tid < NH) {
            float s = 0.f;
            #pragma unroll
            for (int m = 0; m < 12; m++) s += sq[tid * 12 + m];
            (w == 0 ? g_qq : g_kk)[(b * NH + tid) * Ll + i] = s;
        }
        __syncthreads();
    }
}

// ---------------- kernel 2: pre-logit = scaled (scalar qk + point term), grid (16, 6) ----------------
__global__ __launch_bounds__(256) void qk_kernel(const float* __restrict__ gamma)
{
    int bn = blockIdx.x;                    // b*8+n
    int j0 = blockIdx.y * 64;
    int tid = threadIdx.x;
    __shared__ __align__(16) float qs_s[Ll * DHSc];   // 24KB
    __shared__ __align__(16) float qp_s[Ll * NPC];    // 18KB
    __shared__ float qq_s[Ll];

    {
        const float4* src = (const float4*)&g_qs[(size_t)bn * Ll * DHSc];
        float4* dst = (float4*)qs_s;
        for (int m = tid; m < Ll * DHSc / 4; m += 256) dst[m] = src[m];
    }
    {
        const float4* src = (const float4*)&g_qp[(size_t)bn * Ll * NPC];
        float4* dst = (float4*)qp_s;
        for (int m = tid; m < Ll * NPC / 4; m += 256) dst[m] = src[m];
    }
    for (int m = tid; m < Ll; m += 256) qq_s[m] = g_qq[bn * Ll + m];
    __syncthreads();

    int j = j0 + (tid & 63);
    int iq = tid >> 6;                      // i-quarter
    float g2 = 0.07216878364870322f * gamma[bn & 7];   // 0.57735*0.125*gamma
    const float4* kr = (const float4*)&g_ks[((size_t)bn * Ll + j) * DHSc];
    float4 k0 = kr[0], k1 = kr[1], k2 = kr[2], k3 = kr[3];
    const float4* kpr = (const float4*)&g_kp[((size_t)bn * Ll + j) * NPC];
    float4 p0 = kpr[0], p1 = kpr[1], p2 = kpr[2];
    float kkv = g_kk[bn * Ll + j];
    float* outb = &g_logit[((size_t)bn * Ll) * Ll + j];
    #pragma unroll 2
    for (int ii = 0; ii < 96; ii++) {
        int i = iq * 96 + ii;
        const float4* qr = (const float4*)&qs_s[i * DHSc];
        float4 q0 = qr[0], q1 = qr[1], q2 = qr[2], q3 = qr[3];
        float s = q0.x*k0.x + q0.y*k0.y + q0.z*k0.z + q0.w*k0.w
                + q1.x*k1.x + q1.y*k1.y + q1.z*k1.z + q1.w*k1.w
                + q2.x*k2.x + q2.y*k2.y + q2.z*k2.z + q2.w*k2.w
                + q3.x*k3.x + q3.y*k3.y + q3.z*k3.z + q3.w*k3.w;
        const float4* qpr = (const float4*)&qp_s[i * NPC];
        float4 a0 = qpr[0], a1 = qpr[1], a2 = qpr[2];
        float cr = a0.x*p0.x + a0.y*p0.y + a0.z*p0.z + a0.w*p0.w
                 + a1.x*p1.x + a1.y*p1.y + a1.z*p1.z + a1.w*p1.w
                 + a2.x*p2.x + a2.y*p2.y + a2.z*p2.z + a2.w*p2.w;
        float d2 = qq_s[i] + kkv - 2.f * cr;
        outb[(size_t)i * Ll] = 0.14433756729740643f * s - g2 * d2;
    }
}

// ---------------- kernel 3: fused flash attention over e (single e pass) ----------------
__global__ __launch_bounds__(256) void fused_kernel(
    const float* __restrict__ e, const float* __restrict__ Wb,
    const float* __restrict__ r, const float* __restrict__ t)
{
    int bi = blockIdx.x;
    int b = bi / Ll, i = bi % Ll;
    int tid = threadIdx.x;
    int warp = tid >> 5, lane = tid & 31;

    __shared__ __align__(16) float buf[JC * ESTR];    // e tile (25344B); reused as pair-reduce buffer
    __shared__ __align__(16) float attn_s[NH * Ll];   // p = exp(l - m_chunk), per head
    __shared__ __align__(16) float wbt[NH * ESTR];    // only first 128 of each row used
    __shared__ float scale_s[NH];
    __shared__ float cs_m[NCH * NH];
    __shared__ float cfac[NCH * NH];
    __shared__ float sinv[NH];
    __shared__ float rs[9], ts[3];
    __shared__ float op_s[96], opl2[96];

    // Wb transposed [n][d]
    for (int m = tid; m < Dd * NH; m += 256) {
        int d = m >> 3, n = m & 7;
        wbt[n * ESTR + d] = Wb[m];
    }
    if (tid < 9) rs[tid] = r[bi * 9 + tid];
    else if (tid >= 16 && tid < 19) ts[tid - 16] = t[bi * 3 + (tid - 16)];

    float m_run = -1e30f, s_run = 0.f;
    float acc[NH][4];
    #pragma unroll
    for (int n = 0; n < NH; n++) { acc[n][0]=0.f; acc[n][1]=0.f; acc[n][2]=0.f; acc[n][3]=0.f; }

    for (int c = 0; c < NCH; c++) {
        int j0 = c * JC;
        __syncthreads();   // buf free (prev pair done), wbt ready on first iter
        // load e chunk (JC x 128) + preload pre-logits into attn_s chunk region
        {
            const float4* esrc = (const float4*)(e + ((size_t)bi * Ll + j0) * Dd);
            for (int m = tid; m < JC * 32; m += 256) {
                int row = m >> 5, dq = m & 31;
                *(float4*)&buf[row * ESTR + dq * 4] = esrc[m];
            }
            for (int m = tid; m < NH * JC; m += 256) {
                int n = m / JC, jl = m - n * JC;
                attn_s[n * Ll + j0 + jl] =
                    g_logit[((size_t)(b * NH + n) * Ll + i) * Ll + j0 + jl];
            }
        }
        __syncthreads();
        // logit phase: bias from smem dot + add to preloaded pre-logit
        if (tid < JC * 4) {
            int jl = tid >> 2, g = tid & 3;
            const float* er = &buf[jl * ESTR];
            const float* w0 = &wbt[g * ESTR];
            const float* w1 = &wbt[(g + 4) * ESTR];
            float b0 = 0.f, b1 = 0.f;
            #pragma unroll 8
            for (int d = 0; d < Dd; d += 4) {
                float4 ev = *(const float4*)&er[d];
                float4 wa = *(const float4*)&w0[d];
                float4 wc = *(const float4*)&w1[d];
                b0 += ev.x * wa.x + ev.y * wa.y + ev.z * wa.z + ev.w * wa.w;
                b1 += ev.x * wc.x + ev.y * wc.y + ev.z * wc.z + ev.w * wc.w;
            }
            attn_s[g * Ll + j0 + jl]       += 0.5773502691896258f * b0;
            attn_s[(g + 4) * Ll + j0 + jl] += 0.5773502691896258f * b1;
        }
        __syncthreads();
        // online softmax chunk update: warp w = head w
        {
            float l0 = attn_s[warp * Ll + j0 + lane];
            float l1 = (lane < JC - 32) ? attn_s[warp * Ll + j0 + 32 + lane] : -1e30f;
            float cm = fmaxf(l0, l1);
            #pragma unroll
            for (int off = 16; off > 0; off >>= 1)
                cm = fmaxf(cm, __shfl_xor_sync(0xffffffffu, cm, off));
            float m_new = fmaxf(m_run, cm);
            float pe0 = __expf(l0 - m_new);
            float pe1 = (lane < JC - 32) ? __expf(l1 - m_new) : 0.f;
            attn_s[warp * Ll + j0 + lane] = pe0;
            if (lane < JC - 32) attn_s[warp * Ll + j0 + 32 + lane] = pe1;
            float ps = pe0 + pe1;
            #pragma unroll
            for (int off = 16; off > 0; off >>= 1)
                ps += __shfl_xor_sync(0xffffffffu, ps, off);
            float sc = __expf(m_run - m_new);
            s_run = s_run * sc + ps;
            if (lane == 0) { scale_s[warp] = sc; cs_m[c * NH + warp] = m_new; }
            m_run = m_new;
        }
        __syncthreads();
        // pair accumulation: warp w handles 6 j-rows; each e element read once from smem
        {
            #pragma unroll
            for (int n = 0; n < NH; n++) {
                float sc = scale_s[n];
                acc[n][0] *= sc; acc[n][1] *= sc; acc[n][2] *= sc; acc[n][3] *= sc;
            }
            int jb = warp * 6;
            #pragma unroll
            for (int jj = 0; jj < 6; jj++) {
                int jl = jb + jj;
                float4 ev = *(const float4*)&buf[jl * ESTR + lane * 4];
                int j = j0 + jl;
                #pragma unroll
                for (int n = 0; n < NH; n++) {
                    float p = attn_s[n * Ll + j];
                    acc[n][0] += p * ev.x; acc[n][1] += p * ev.y;
                    acc[n][2] += p * ev.z; acc[n][3] += p * ev.w;
                }
            }
        }
    }
    __syncthreads();

    // finalize per-head normalizers + per-chunk correction factors
    {
        float inv = 1.f / s_run;      // uniform within warp
        if (lane == 0) sinv[warp] = inv;
        if (lane < NCH)
            cfac[lane * NH + warp] = __expf(cs_m[lane * NH + warp] - m_run) * inv;
    }
    __syncthreads();

    float* feat = &g_feat[bi * FEAT];

    // out_scalar (tid<128) and op point accumulation (128<=tid<224), chunk-corrected
    if (tid < 128) {
        int n = tid >> 4, d = tid & 15;
        float a = 0.f;
        for (int c = 0; c < NCH; c++) {
            const float* pr = &attn_s[n * Ll + c * JC];
            const float* vr = &g_vs[((size_t)(b * NH + n) * Ll + c * JC) * DHSc + d];
            float part = 0.f;
            #pragma unroll 8
            for (int jj = 0; jj < JC; jj++) part += pr[jj] * vr[jj * DHSc];
            a += part * cfac[c * NH + n];
        }
        feat[tid] = a;
    } else if (tid < 224) {
        int m = tid - 128, n = m / 12, pc = m % 12;
        float a = 0.f;
        for (int c = 0; c < NCH; c++) {
            const float* pr = &attn_s[n * Ll + c * JC];
            const float* vr = &g_vp[((size_t)(b * NH + n) * Ll + c * JC) * NPC + pc];
            float part = 0.f;
            #pragma unroll 8
            for (int jj = 0; jj < JC; jj++) part += pr[jj] * vr[jj * NPC];
            a += part * cfac[c * NH + n];
        }
        op_s[m] = a;
    }
    __syncthreads();

    // op_local (inverse rotation) + norm
    if (tid < 96) {
        int pc = tid % 12, nb = tid - pc;
        int p3 = (pc / 3) * 3, cc = pc % 3;
        const float* ob = &op_s[nb + p3];
        float v = (ob[0] - ts[0]) * rs[cc * 3 + 0]
                + (ob[1] - ts[1]) * rs[cc * 3 + 1]
                + (ob[2] - ts[2]) * rs[cc * 3 + 2];
        feat[1152 + tid] = v;
        opl2[tid] = v * v;
    }
    __syncthreads();
    if (tid < 32) {
        int base = (tid >> 2) * 12 + (tid & 3) * 3;
        feat[1248 + tid] = sqrtf(opl2[base] + opl2[base + 1] + opl2[base + 2]);
    }

    // cross-warp reduction of pair accumulators (tree in buf), then normalized write
    #pragma unroll
    for (int stride = 4; stride >= 1; stride >>= 1) {
        if (warp >= stride && warp < 2 * stride) {
            float* dstb = &buf[(warp - stride) * 1024];
            #pragma unroll
            for (int n = 0; n < NH; n++)
                *(float4*)&dstb[n * 128 + lane * 4] =
                    make_float4(acc[n][0], acc[n][1], acc[n][2], acc[n][3]);
        }
        __syncthreads();
        if (warp < stride) {
            const float* srcb = &buf[warp * 1024];
            #pragma unroll
            for (int n = 0; n < NH; n++) {
                float4 v = *(const float4*)&srcb[n * 128 + lane * 4];
                acc[n][0] += v.x; acc[n][1] += v.y; acc[n][2] += v.z; acc[n][3] += v.w;
            }
        }
        __syncthreads();
    }
    if (warp == 0) {
        #pragma unroll
        for (int n = 0; n < NH; n++) {
            float iv = sinv[n];
            *(float4*)&feat[128 + n * 128 + lane * 4] =
                make_float4(acc[n][0] * iv, acc[n][1] * iv, acc[n][2] * iv, acc[n][3] * iv);
        }
    }
}

// ---------------- kernel 4a: partial out GEMM (k-split) ----------------
#define TMR 8
#define KC 64
__global__ __launch_bounds__(256) void out_part_kernel(const float* __restrict__ Wo)
{
    int row0 = blockIdx.x * TMR;
    int kbase = blockIdx.y * (FEAT / KSPLIT);
    int tid = threadIdx.x;
    int tx = tid & 31;
    int ty = tid >> 5;
    __shared__ __align__(16) float As[TMR * KC];
    __shared__ __align__(16) float Bs[KC * Dd];
    float acc0 = 0.f, acc1 = 0.f, acc2 = 0.f, acc3 = 0.f;
    #pragma unroll
    for (int tile = 0; tile < (FEAT / KSPLIT) / KC; tile++) {
        int k0 = kbase + tile * KC;
        for (int m = tid; m < TMR * KC; m += 256) {
            int rr = m >> 6, kk = m & (KC - 1);
            As[m] = g_feat[(row0 + rr) * FEAT + k0 + kk];
        }
        {
            const float4* wsrc = (const float4*)(Wo + (size_t)k0 * Dd);
            float4* bdst = (float4*)Bs;
            for (int m = tid; m < KC * Dd / 4; m += 256) bdst[m] = wsrc[m];
        }
        __syncthreads();
        #pragma unroll 4
        for (int kk = 0; kk < KC; kk++) {
            float av = As[ty * KC + kk];
            float4 bv = *(const float4*)&Bs[kk * Dd + tx * 4];
            acc0 += av * bv.x; acc1 += av * bv.y; acc2 += av * bv.z; acc3 += av * bv.w;
        }
        __syncthreads();
    }
    int row = row0 + ty;
    *(float4*)&g_part[((size_t)blockIdx.y * OUTROWS + row) * Dd + tx * 4] =
        make_float4(acc0, acc1, acc2, acc3);
}

// ---------------- kernel 4b: reduce partials + bias ----------------
__global__ __launch_bounds__(256) void out_reduce_kernel(
    const float* __restrict__ bo, float* __restrict__ out)
{
    int idx = blockIdx.x * 256 + threadIdx.x;
    int c = idx & (Dd - 1);
    float a = bo[c];
    #pragma unroll
    for (int s = 0; s < KSPLIT; s++) a += g_part[s * (OUTROWS * Dd) + idx];
    out[idx] = a;
}

// ---------------- launch ----------------
extern "C" void kernel_launch(void* const* d_in, const int* in_sizes, int n_in,
                              void* d_out, int out_size) {
    const float* x     = (const float*)d_in[0];
    const float* e     = (const float*)d_in[1];
    const float* r     = (const float*)d_in[2];
    const float* t     = (const float*)d_in[3];
    const float* Wqs   = (const float*)d_in[4];
    const float* Wks   = (const float*)d_in[5];
    const float* Wvs   = (const float*)d_in[6];
    const float* Wb    = (const float*)d_in[7];
    const float* Wqp   = (const float*)d_in[8];
    const float* Wkp   = (const float*)d_in[9];
    const float* Wvp   = (const float*)d_in[10];
    const float* gamma = (const float*)d_in[11];
    const float* Wo    = (const float*)d_in[12];
    const float* bo    = (const float*)d_in[13];
    float* out = (float*)d_out;

    proj_kernel<<<Bb * Ll, 128>>>(x, r, t, Wqs, Wks, Wvs, Wqp, Wkp, Wvp);
    qk_kernel<<<dim3(Bb * NH, Ll / 64), 256>>>(gamma);
    fused_kernel<<<Bb * Ll, 256>>>(e, Wb, r, t);
    out_part_kernel<<<dim3((Bb * Ll) / TMR, KSPLIT), 256>>>(Wo);
    out_reduce_kernel<<<(OUTROWS * Dd) / 256, 256>>>(bo, out);
}

// round 8
// speedup vs baseline: 1.1994x; 1.1577x over previous
#include <cuda_runtime.h>
#include <math.h>
#include <stdint.h>

#define Bb 2
#define Ll 384
#define Dd 128
#define NH 8
#define DHSc 16
#define NPC 12            // DHP*3
#define FEAT 1280
#define KSPLIT 5
#define OUTROWS (Bb*Ll)
#define JC 24             // j-chunk for fused kernel
#define NCH (Ll/JC)       // 16 chunks
#define ESTR 132          // padded smem row stride (floats) for e tiles

// ---------------- scratch (no allocations allowed) ----------------
static __device__ __align__(16) float g_qs[Bb*NH*Ll*DHSc];
static __device__ __align__(16) float g_ks[Bb*NH*Ll*DHSc];
static __device__ __align__(16) float g_vs[Bb*NH*Ll*DHSc];
static __device__ __align__(16) float g_qp[Bb*NH*Ll*NPC];
static __device__ __align__(16) float g_kp[Bb*NH*Ll*NPC];
static __device__ __align__(16) float g_vp[Bb*NH*Ll*NPC];
static __device__ __align__(16) float g_qq[Bb*NH*Ll];
static __device__ __align__(16) float g_kk[Bb*NH*Ll];
static __device__ __align__(16) float g_logit[(size_t)Bb*NH*Ll*Ll];  // pre-logit (scalar+point terms)
static __device__ __align__(16) float g_feat[Bb*Ll*FEAT];
static __device__ __align__(16) float g_part[KSPLIT*OUTROWS*Dd];

__device__ __forceinline__ void cpa16(uint32_t dst, const void* src) {
    asm volatile("cp.async.cg.shared.global [%0], [%1], 16;" :: "r"(dst), "l"(src));
}

// ---------------- kernel 1: projections ----------------
__global__ __launch_bounds__(128) void proj_kernel(
    const float* __restrict__ x, const float* __restrict__ r, const float* __restrict__ t,
    const float* __restrict__ Wqs, const float* __restrict__ Wks, const float* __restrict__ Wvs,
    const float* __restrict__ Wqp, const float* __restrict__ Wkp, const float* __restrict__ Wvp)
{
    int bi = blockIdx.x;
    int b = bi / Ll, i = bi % Ll;
    int tid = threadIdx.x;
    __shared__ float xs[Dd];
    __shared__ float rs[9], ts[3];
    __shared__ float xp[96];
    __shared__ float sq[96];
    xs[tid] = x[bi * Dd + tid];
    if (tid < 9) rs[tid] = r[bi * 9 + tid];
    else if (tid >= 16 && tid < 19) ts[tid - 16] = t[bi * 3 + (tid - 16)];
    __syncthreads();
    {
        float a0 = 0.f, a1 = 0.f, a2 = 0.f;
        #pragma unroll 4
        for (int k = 0; k < Dd; k++) {
            float xv = xs[k];
            a0 += xv * Wqs[k * Dd + tid];
            a1 += xv * Wks[k * Dd + tid];
            a2 += xv * Wvs[k * Dd + tid];
        }
        int n = tid >> 4, d = tid & 15;
        int o = ((b * NH + n) * Ll + i) * DHSc + d;
        g_qs[o] = a0; g_ks[o] = a1; g_vs[o] = a2;
    }
    #pragma unroll
    for (int w = 0; w < 3; w++) {
        const float* W = (w == 0) ? Wqp : (w == 1) ? Wkp : Wvp;
        float* dst = (w == 0) ? g_qp : (w == 1) ? g_kp : g_vp;
        if (tid < 96) {
            float a = 0.f;
            #pragma unroll 4
            for (int k = 0; k < Dd; k++) a += xs[k] * W[k * 96 + tid];
            xp[tid] = a;
        }
        __syncthreads();
        if (tid < 96) {
            int n = tid / 12, pc = tid % 12, p = pc / 3, c = pc % 3;
            const float* xb = &xp[n * 12 + p * 3];
            float v = xb[0] * rs[c] + xb[1] * rs[3 + c] + xb[2] * rs[6 + c] + ts[c];
            dst[((b * NH + n) * Ll + i) * NPC + pc] = v;
            sq[tid] = v * v;
        }
        __syncthreads();
        if (w < 2 && tid < NH) {
            float s = 0.f;
            #pragma unroll
            for (int m = 0; m < 12; m++) s += sq[tid * 12 + m];
            (w == 0 ? g_qq : g_kk)[(b * NH + tid) * Ll + i] = s;
        }
        __syncthreads();
    }
}

// ---------------- kernel 2: pre-logit, grid (16, 6, 4) ----------------
__global__ __launch_bounds__(256) void qk_kernel(const float* __restrict__ gamma)
{
    int bn = blockIdx.x;                    // b*8+n
    int j0 = blockIdx.y * 64;
    int i0 = blockIdx.z * 96;
    int tid = threadIdx.x;
    __shared__ __align__(16) float qs_s[96 * DHSc];
    __shared__ __align__(16) float qp_s[96 * NPC];
    __shared__ float qq_s[96];

    {
        const float4* src = (const float4*)&g_qs[((size_t)bn * Ll + i0) * DHSc];
        float4* dst = (float4*)qs_s;
        for (int m = tid; m < 96 * DHSc / 4; m += 256) dst[m] = src[m];
    }
    {
        const float4* src = (const float4*)&g_qp[((size_t)bn * Ll + i0) * NPC];
        float4* dst = (float4*)qp_s;
        for (int m = tid; m < 96 * NPC / 4; m += 256) dst[m] = src[m];
    }
    if (tid < 96) qq_s[tid] = g_qq[bn * Ll + i0 + tid];
    __syncthreads();

    int j = j0 + (tid & 63);
    int ig = tid >> 6;
    float g2 = 0.07216878364870322f * gamma[bn & 7];   // 0.57735*0.125*gamma
    const float4* kr = (const float4*)&g_ks[((size_t)bn * Ll + j) * DHSc];
    float4 k0 = kr[0], k1 = kr[1], k2 = kr[2], k3 = kr[3];
    const float4* kpr = (const float4*)&g_kp[((size_t)bn * Ll + j) * NPC];
    float4 p0 = kpr[0], p1 = kpr[1], p2 = kpr[2];
    float kkv = g_kk[bn * Ll + j];
    float* outb = &g_logit[((size_t)bn * Ll + i0) * Ll + j];
    #pragma unroll 4
    for (int ii = 0; ii < 24; ii++) {
        int il = ig * 24 + ii;
        const float4* qr = (const float4*)&qs_s[il * DHSc];
        float4 q0 = qr[0], q1 = qr[1], q2 = qr[2], q3 = qr[3];
        float s = q0.x*k0.x + q0.y*k0.y + q0.z*k0.z + q0.w*k0.w
                + q1.x*k1.x + q1.y*k1.y + q1.z*k1.z + q1.w*k1.w
                + q2.x*k2.x + q2.y*k2.y + q2.z*k2.z + q2.w*k2.w
                + q3.x*k3.x + q3.y*k3.y + q3.z*k3.z + q3.w*k3.w;
        const float4* qpr = (const float4*)&qp_s[il * NPC];
        float4 a0 = qpr[0], a1 = qpr[1], a2 = qpr[2];
        float cr = a0.x*p0.x + a0.y*p0.y + a0.z*p0.z + a0.w*p0.w
                 + a1.x*p1.x + a1.y*p1.y + a1.z*p1.z + a1.w*p1.w
                 + a2.x*p2.x + a2.y*p2.y + a2.z*p2.z + a2.w*p2.w;
        float d2 = qq_s[il] + kkv - 2.f * cr;
        outb[(size_t)il * Ll] = 0.14433756729740643f * s - g2 * d2;
    }
}

// ---------------- kernel 3: fused flash attention over e (single e pass, cp.async pipelined) ----------------
__global__ __launch_bounds__(256) void fused_kernel(
    const float* __restrict__ e, const float* __restrict__ Wb,
    const float* __restrict__ r, const float* __restrict__ t)
{
    int bi = blockIdx.x;
    int b = bi / Ll, i = bi % Ll;
    int tid = threadIdx.x;
    int warp = tid >> 5, lane = tid & 31;

    __shared__ __align__(16) float buf[2][JC * ESTR]; // double-buffered e tiles; buf[0..] reused for tree
    __shared__ __align__(16) float attn_s[NH * Ll];   // p = exp(l - m_run), per head
    __shared__ __align__(16) float wbt[NH * ESTR];    // Wb transposed, first 128 of each row used
    __shared__ float scale_s[NH];
    __shared__ float cs_m[NCH * NH];
    __shared__ float cfac[NCH * NH];
    __shared__ float sinv[NH];
    __shared__ float rs[9], ts[3];
    __shared__ float op_s[96], opl2[96];

    for (int m = tid; m < Dd * NH; m += 256) {
        int d = m >> 3, n = m & 7;
        wbt[n * ESTR + d] = Wb[m];
    }
    if (tid < 9) rs[tid] = r[bi * 9 + tid];
    else if (tid >= 16 && tid < 19) ts[tid - 16] = t[bi * 3 + (tid - 16)];

    uint32_t buf_sa[2];
    buf_sa[0] = (uint32_t)__cvta_generic_to_shared(&buf[0][0]);
    buf_sa[1] = (uint32_t)__cvta_generic_to_shared(&buf[1][0]);
    const float4* ebase = (const float4*)(e + (size_t)bi * Ll * Dd);

    // prologue: issue chunk 0
    for (int m = tid; m < JC * 32; m += 256) {
        int row = m >> 5, dq = m & 31;
        cpa16(buf_sa[0] + (row * ESTR + dq * 4) * 4, ebase + m);
    }
    asm volatile("cp.async.commit_group;");

    float m_run = -1e30f, s_run = 0.f;
    float acc[NH][4];
    #pragma unroll
    for (int n = 0; n < NH; n++) { acc[n][0]=0.f; acc[n][1]=0.f; acc[n][2]=0.f; acc[n][3]=0.f; }

    int jl = tid >> 3, g = tid & 7;   // bias task mapping (tid < 192)

    for (int c = 0; c < NCH; c++) {
        int cur = c & 1;
        int j0 = c * JC;
        __syncthreads();               // pair(c-1) done reading buf[1^cur]
        if (c + 1 < NCH) {
            const float4* esrc = ebase + (c + 1) * JC * 32;
            uint32_t bs = buf_sa[1 ^ cur];
            for (int m = tid; m < JC * 32; m += 256) {
                int row = m >> 5, dq = m & 31;
                cpa16(bs + (row * ESTR + dq * 4) * 4, esrc + m);
            }
            asm volatile("cp.async.commit_group;");
        }
        // pre-logit load for chunk c (L2-hot), hoisted before the wait
        float lv = 0.f;
        if (tid < 192)
            lv = g_logit[((size_t)(b * NH + g) * Ll + i) * Ll + j0 + jl];
        if (c + 1 < NCH) asm volatile("cp.async.wait_group 1;");
        else             asm volatile("cp.async.wait_group 0;");
        __syncthreads();               // buf[cur] visible

        // bias phase: one (jl, head) per thread (192 threads)
        if (tid < 192) {
            const float* er = &buf[cur][jl * ESTR];
            const float* w0 = &wbt[g * ESTR];
            float bsum = 0.f;
            #pragma unroll 8
            for (int d = 0; d < Dd; d += 4) {
                float4 ev = *(const float4*)&er[d];
                float4 wa = *(const float4*)&w0[d];
                bsum += ev.x * wa.x + ev.y * wa.y + ev.z * wa.z + ev.w * wa.w;
            }
            attn_s[g * Ll + j0 + jl] = lv + 0.5773502691896258f * bsum;
        }
        __syncthreads();

        // online softmax chunk update: warp w = head w
        {
            float l0 = (lane < JC) ? attn_s[warp * Ll + j0 + lane] : -1e30f;
            float cm = l0;
            #pragma unroll
            for (int off = 16; off > 0; off >>= 1)
                cm = fmaxf(cm, __shfl_xor_sync(0xffffffffu, cm, off));
            float m_new = fmaxf(m_run, cm);
            float pe0 = (lane < JC) ? __expf(l0 - m_new) : 0.f;
            if (lane < JC) attn_s[warp * Ll + j0 + lane] = pe0;
            float ps = pe0;
            #pragma unroll
            for (int off = 16; off > 0; off >>= 1)
                ps += __shfl_xor_sync(0xffffffffu, ps, off);
            float sc = __expf(m_run - m_new);
            s_run = s_run * sc + ps;
            if (lane == 0) { scale_s[warp] = sc; cs_m[c * NH + warp] = m_new; }
            m_run = m_new;
        }
        __syncthreads();

        // pair accumulation: warp w handles 3 j-rows
        {
            #pragma unroll
            for (int n = 0; n < NH; n++) {
                float sc = scale_s[n];
                acc[n][0] *= sc; acc[n][1] *= sc; acc[n][2] *= sc; acc[n][3] *= sc;
            }
            int jb = warp * 3;
            #pragma unroll
            for (int jj = 0; jj < 3; jj++) {
                int jloc = jb + jj;
                float4 ev = *(const float4*)&buf[cur][jloc * ESTR + lane * 4];
                int j = j0 + jloc;
                #pragma unroll
                for (int n = 0; n < NH; n++) {
                    float p = attn_s[n * Ll + j];
                    acc[n][0] += p * ev.x; acc[n][1] += p * ev.y;
                    acc[n][2] += p * ev.z; acc[n][3] += p * ev.w;
                }
            }
        }
    }
    __syncthreads();

    // finalize normalizers + per-chunk correction factors
    {
        float inv = 1.f / s_run;
        if (lane == 0) sinv[warp] = inv;
        if (lane < NCH)
            cfac[lane * NH + warp] = __expf(cs_m[lane * NH + warp] - m_run) * inv;
    }
    __syncthreads();

    float* feat = &g_feat[bi * FEAT];

    // out_scalar (tid<128) and op point accumulation (128<=tid<224), chunk-corrected
    if (tid < 128) {
        int n = tid >> 4, d = tid & 15;
        float a = 0.f;
        for (int c = 0; c < NCH; c++) {
            const float* pr = &attn_s[n * Ll + c * JC];
            const float* vr = &g_vs[((size_t)(b * NH + n) * Ll + c * JC) * DHSc + d];
            float part = 0.f;
            #pragma unroll
            for (int jj = 0; jj < JC; jj++) part += pr[jj] * vr[jj * DHSc];
            a += part * cfac[c * NH + n];
        }
        feat[tid] = a;
    } else if (tid < 224) {
        int m = tid - 128, n = m / 12, pc = m % 12;
        float a = 0.f;
        for (int c = 0; c < NCH; c++) {
            const float* pr = &attn_s[n * Ll + c * JC];
            const float* vr = &g_vp[((size_t)(b * NH + n) * Ll + c * JC) * NPC + pc];
            float part = 0.f;
            #pragma unroll
            for (int jj = 0; jj < JC; jj++) part += pr[jj] * vr[jj * NPC];
            a += part * cfac[c * NH + n];
        }
        op_s[m] = a;
    }
    __syncthreads();

    // op_local (inverse rotation) + norm
    if (tid < 96) {
        int pc = tid % 12, nb = tid - pc;
        int p3 = (pc / 3) * 3, cc = pc % 3;
        const float* ob = &op_s[nb + p3];
        float v = (ob[0] - ts[0]) * rs[cc * 3 + 0]
                + (ob[1] - ts[1]) * rs[cc * 3 + 1]
                + (ob[2] - ts[2]) * rs[cc * 3 + 2];
        feat[1152 + tid] = v;
        opl2[tid] = v * v;
    }
    __syncthreads();
    if (tid < 32) {
        int base = (tid >> 2) * 12 + (tid & 3) * 3;
        feat[1248 + tid] = sqrtf(opl2[base] + opl2[base + 1] + opl2[base + 2]);
    }

    // cross-warp reduction of pair accumulators (tree in buf), then normalized write
    float* tree = &buf[0][0];
    #pragma unroll
    for (int stride = 4; stride >= 1; stride >>= 1) {
        if (warp >= stride && warp < 2 * stride) {
            float* dstb = &tree[(warp - stride) * 1024];
            #pragma unroll
            for (int n = 0; n < NH; n++)
                *(float4*)&dstb[n * 128 + lane * 4] =
                    make_float4(acc[n][0], acc[n][1], acc[n][2], acc[n][3]);
        }
        __syncthreads();
        if (warp < stride) {
            const float* srcb = &tree[warp * 1024];
            #pragma unroll
            for (int n = 0; n < NH; n++) {
                float4 v = *(const float4*)&srcb[n * 128 + lane * 4];
                acc[n][0] += v.x; acc[n][1] += v.y; acc[n][2] += v.z; acc[n][3] += v.w;
            }
        }
        __syncthreads();
    }
    if (warp == 0) {
        #pragma unroll
        for (int n = 0; n < NH; n++) {
            float iv = sinv[n];
            *(float4*)&feat[128 + n * 128 + lane * 4] =
                make_float4(acc[n][0] * iv, acc[n][1] * iv, acc[n][2] * iv, acc[n][3] * iv);
        }
    }
}

// ---------------- kernel 4a: partial out GEMM (k-split), 2 rows/thread ----------------
#define TMR 16
#define KC 64
__global__ __launch_bounds__(256) void out_part_kernel(const float* __restrict__ Wo)
{
    int row0 = blockIdx.x * TMR;
    int kbase = blockIdx.y * (FEAT / KSPLIT);
    int tid = threadIdx.x;
    int tx = tid & 31;
    int ty = tid >> 5;       // 0..7 → rows 2*ty, 2*ty+1
    __shared__ __align__(16) float As[TMR * KC];
    __shared__ __align__(16) float Bs[KC * Dd];
    float a00=0.f,a01=0.f,a02=0.f,a03=0.f;
    float a10=0.f,a11=0.f,a12=0.f,a13=0.f;
    #pragma unroll
    for (int tile = 0; tile < (FEAT / KSPLIT) / KC; tile++) {
        int k0 = kbase + tile * KC;
        {
            int rr = tid >> 4, q = tid & 15;    // 16 rows x 16 float4
            *(float4*)&As[rr * KC + q * 4] =
                *(const float4*)&g_feat[(row0 + rr) * FEAT + k0 + q * 4];
        }
        {
            const float4* wsrc = (const float4*)(Wo + (size_t)k0 * Dd);
            float4* bdst = (float4*)Bs;
            #pragma unroll
            for (int m = 0; m < 8; m++) bdst[tid + m * 256] = wsrc[tid + m * 256];
        }
        __syncthreads();
        #pragma unroll 4
        for (int kk = 0; kk < KC; kk++) {
            float av0 = As[(ty * 2) * KC + kk];
            float av1 = As[(ty * 2 + 1) * KC + kk];
            float4 bv = *(const float4*)&Bs[kk * Dd + tx * 4];
            a00 += av0 * bv.x; a01 += av0 * bv.y; a02 += av0 * bv.z; a03 += av0 * bv.w;
            a10 += av1 * bv.x; a11 += av1 * bv.y; a12 += av1 * bv.z; a13 += av1 * bv.w;
        }
        __syncthreads();
    }
    size_t base = (size_t)blockIdx.y * OUTROWS * Dd;
    *(float4*)&g_part[base + (size_t)(row0 + ty * 2) * Dd + tx * 4] =
        make_float4(a00, a01, a02, a03);
    *(float4*)&g_part[base + (size_t)(row0 + ty * 2 + 1) * Dd + tx * 4] =
        make_float4(a10, a11, a12, a13);
}

// ---------------- kernel 4b: reduce partials + bias ----------------
__global__ __launch_bounds__(256) void out_reduce_kernel(
    const float* __restrict__ bo, float* __restrict__ out)
{
    int idx = blockIdx.x * 256 + threadIdx.x;
    int c = idx & (Dd - 1);
    float a = bo[c];
    #pragma unroll
    for (int s = 0; s < KSPLIT; s++) a += g_part[s * (OUTROWS * Dd) + idx];
    out[idx] = a;
}

// ---------------- launch ----------------
extern "C" void kernel_launch(void* const* d_in, const int* in_sizes, int n_in,
                              void* d_out, int out_size) {
    const float* x     = (const float*)d_in[0];
    const float* e     = (const float*)d_in[1];
    const float* r     = (const float*)d_in[2];
    const float* t     = (const float*)d_in[3];
    const float* Wqs   = (const float*)d_in[4];
    const float* Wks   = (const float*)d_in[5];
    const float* Wvs   = (const float*)d_in[6];
    const float* Wb    = (const float*)d_in[7];
    const float* Wqp   = (const float*)d_in[8];
    const float* Wkp   = (const float*)d_in[9];
    const float* Wvp   = (const float*)d_in[10];
    const float* gamma = (const float*)d_in[11];
    const float* Wo    = (const float*)d_in[12];
    const float* bo    = (const float*)d_in[13];
    float* out = (float*)d_out;

    proj_kernel<<<Bb * Ll, 128>>>(x, r, t, Wqs, Wks, Wvs, Wqp, Wkp, Wvp);
    qk_kernel<<<dim3(Bb * NH, Ll / 64, 4), 256>>>(gamma);
    fused_kernel<<<Bb * Ll, 256>>>(e, Wb, r, t);
    out_part_kernel<<<dim3((Bb * Ll) / TMR, KSPLIT), 256>>>(Wo);
    out_reduce_kernel<<<(OUTROWS * Dd) / 256, 256>>>(bo, out);
}